// round 3
// baseline (speedup 1.0000x reference)
#include <cuda_runtime.h>
#include <cstdint>

// TotalDegree: out[b,t] = monomials of degree<=4 over x[b,0..7], 495 terms,
// lexicographic multiset (preorder-DFS) order.
//
// R3: persistent warps, each warp loops over many rows. The (lo,hi) pair-id
// table is preloaded ONCE per warp into 32 registers holding absolute 32-bit
// shared-memory ADDRESSES, so the per-row inner loop is just:
//   LDS, LDS, FMUL, STG[imm]   (4 inst, 3 L1 wavefronts per 32 terms)

#define NTERMS 495
#define NVALS  45          // pair values (a,b), 0 <= a <= b <= 8; index 8 == 1.0
#define DIM    8
#define NITER  16          // term t = lane + 32*i; padded to 512 with identity
#define VSTRIDE 48         // floats per warp's V slot
#define NBLOCKS 608        // ~4 blocks/SM on 152-SM GB300
#define NTHREADS 256

constexpr int vid(int a, int b) { return a * 9 - a * (a - 1) / 2 + (b - a); }

struct alignas(16) OffTbl { unsigned v[32 * NITER]; };  // [lane][iter]: lo*4 | (hi*4)<<16
struct Dec { unsigned char v[NVALS]; };

// Term table in reference order (verified in R1/R2), converted to lane-transposed
// packed byte-offset pairs into the 45-entry pair-value table.
constexpr OffTbl make_off() {
    unsigned short tv[512] = {};
    int n = 0;
    const int one = vid(8, 8);                                   // id 44 -> 1.0
    tv[n++] = (unsigned short)(one | (one << 8));                // degree 0
    for (int a = 0; a < DIM; a++) {
        tv[n++] = (unsigned short)(vid(a, 8) | (one << 8));      // degree 1
        for (int b = a; b < DIM; b++) {
            tv[n++] = (unsigned short)(vid(a, b) | (one << 8));  // degree 2
            for (int c = b; c < DIM; c++) {
                tv[n++] = (unsigned short)(vid(a, b) | (vid(c, 8) << 8));      // deg 3
                for (int d = c; d < DIM; d++)
                    tv[n++] = (unsigned short)(vid(a, b) | (vid(c, d) << 8));  // deg 4
            }
        }
    }
    for (int t = n; t < 512; t++) tv[t] = (unsigned short)(one | (one << 8)); // pad
    OffTbl o{};
    for (int lane = 0; lane < 32; lane++)
        for (int i = 0; i < NITER; i++) {
            const unsigned e = tv[lane + 32 * i];
            o.v[lane * NITER + i] = ((e & 255u) * 4u) | (((e >> 8) * 4u) << 16);
        }
    return o;
}

constexpr Dec make_dec() {
    Dec d{};
    for (int a = 0; a <= 8; a++)
        for (int b = a; b <= 8; b++)
            d.v[vid(a, b)] = (unsigned char)(a | (b << 4));
    return d;
}

__device__ const OffTbl g_off = make_off();
__device__ const Dec    g_dec = make_dec();

__global__ void __launch_bounds__(NTHREADS)
totaldegree_kernel(const float* __restrict__ x, float* __restrict__ out, int nrows) {
    __shared__ float s_v[NTHREADS / 32][VSTRIDE];
    const int warp = threadIdx.x >> 5;
    const int lane = threadIdx.x & 31;
    float* V = s_v[warp];

    // ---- one-time per-warp preload: 32 absolute smem addresses ----
    unsigned alo[NITER], ahi[NITER];
    {
        const unsigned vbase = (unsigned)__cvta_generic_to_shared(V);
        const uint4* tp = reinterpret_cast<const uint4*>(g_off.v + lane * NITER);
        unsigned off[NITER];
        #pragma unroll
        for (int q = 0; q < NITER / 4; q++) {
            const uint4 u = tp[q];
            off[q * 4 + 0] = u.x; off[q * 4 + 1] = u.y;
            off[q * 4 + 2] = u.z; off[q * 4 + 3] = u.w;
        }
        #pragma unroll
        for (int i = 0; i < NITER; i++) {
            alo[i] = vbase + (off[i] & 0xffffu);
            ahi[i] = vbase + (off[i] >> 16);
        }
    }
    const unsigned d0 = g_dec.v[lane];
    const unsigned d1 = g_dec.v[(lane + 32 < NVALS) ? lane + 32 : NVALS - 1];

    const int totalWarps = gridDim.x * (NTHREADS / 32);
    int row = blockIdx.x * (NTHREADS / 32) + warp;

    // prefetch first row's x (lanes 0..7; others hold the identity 1.0)
    float xv = 1.0f;
    if (row < nrows && lane < DIM) xv = x[(size_t)row * DIM + lane];

    while (row < nrows) {
        const int nrow = row + totalWarps;
        float xnext = 1.0f;
        if (nrow < nrows && lane < DIM) xnext = x[(size_t)nrow * DIM + lane];

        // build 45 pair values via shuffles (all-lane shfl, predicated store)
        const float a0 = __shfl_sync(0xffffffffu, xv, d0 & 15u);
        const float b0 = __shfl_sync(0xffffffffu, xv, d0 >> 4);
        const float a1 = __shfl_sync(0xffffffffu, xv, d1 & 15u);
        const float b1 = __shfl_sync(0xffffffffu, xv, d1 >> 4);
        __syncwarp();                       // prior row's reads done before overwrite
        V[lane] = a0 * b0;
        if (lane < NVALS - 32) V[lane + 32] = a1 * b1;
        __syncwarp();                       // writes visible before reads

        float* o = out + (size_t)row * NTERMS + lane;
        #pragma unroll
        for (int i = 0; i < NITER; i++) {
            float va, vb;
            asm volatile("ld.shared.f32 %0, [%1];" : "=f"(va) : "r"(alo[i]));
            asm volatile("ld.shared.f32 %0, [%1];" : "=f"(vb) : "r"(ahi[i]));
            if (i < NITER - 1 || lane < NTERMS - 32 * (NITER - 1))  // lane < 15
                o[32 * i] = va * vb;        // coalesced, immediate-offset STG
        }

        xv = xnext;
        row = nrow;
    }
}

extern "C" void kernel_launch(void* const* d_in, const int* in_sizes, int n_in,
                              void* d_out, int out_size) {
    const float* x = (const float*)d_in[0];
    float* out = (float*)d_out;
    const int nrows = in_sizes[0] / DIM;
    totaldegree_kernel<<<NBLOCKS, NTHREADS>>>(x, out, nrows);
}

// round 4
// speedup vs baseline: 1.0549x; 1.0549x over previous
#include <cuda_runtime.h>
#include <cstdint>

// TotalDegree: out[b,t] = monomials of degree<=4 over x[b,0..7], 495 terms,
// lexicographic multiset (preorder-DFS) order.
//
// R4: R2 structure (one row per warp-iteration, coalesced stores) + the
// (lo,hi) pair-offset table amortized into 16 PACKED registers per warp
// (each holds lo_byteoff | hi_byteoff<<8), with each warp handling 8 rows.
// Inner loop is plain C++ so ptxas can batch the 32 LDS per row.

#define NTERMS 495
#define NVALS  45          // pair values (a,b), 0 <= a <= b <= 8; index 8 == 1.0
#define DIM    8
#define NITER  16          // term t = lane + 32*i (512-padded)
#define RPW    8           // rows per warp
#define NTHREADS 256

constexpr int vid(int a, int b) { return a * 9 - a * (a - 1) / 2 + (b - a); }

struct OffT { unsigned short v[NITER * 32]; };   // [i][lane]: lo*4 | (hi*4)<<8
struct Dec  { unsigned char v[NVALS]; };

constexpr OffT make_off() {
    unsigned short tv[512] = {};
    int n = 0;
    const int one = vid(8, 8);                                   // id 44 -> 1.0
    tv[n++] = (unsigned short)(one | (one << 8));                // degree 0
    for (int a = 0; a < DIM; a++) {
        tv[n++] = (unsigned short)(vid(a, 8) | (one << 8));      // degree 1
        for (int b = a; b < DIM; b++) {
            tv[n++] = (unsigned short)(vid(a, b) | (one << 8));  // degree 2
            for (int c = b; c < DIM; c++) {
                tv[n++] = (unsigned short)(vid(a, b) | (vid(c, 8) << 8));      // deg 3
                for (int d = c; d < DIM; d++)
                    tv[n++] = (unsigned short)(vid(a, b) | (vid(c, d) << 8));  // deg 4
            }
        }
    }
    for (int t = n; t < 512; t++) tv[t] = (unsigned short)(one | (one << 8));
    OffT o{};
    for (int i = 0; i < NITER; i++)
        for (int lane = 0; lane < 32; lane++) {
            const unsigned e = tv[lane + 32 * i];
            // byte offsets into the 45-float V table (<= 176, fits a byte each)
            o.v[i * 32 + lane] =
                (unsigned short)(((e & 255u) * 4u) | (((e >> 8) * 4u) << 8));
        }
    return o;
}

constexpr Dec make_dec() {
    Dec d{};
    for (int a = 0; a <= 8; a++)
        for (int b = a; b <= 8; b++)
            d.v[vid(a, b)] = (unsigned char)(a | (b << 4));
    return d;
}

__device__ const OffT g_off = make_off();
__device__ const Dec  g_dec = make_dec();

__global__ void __launch_bounds__(NTHREADS)
totaldegree_kernel(const float* __restrict__ x, float* __restrict__ out, int nrows) {
    __shared__ float s_v[NTHREADS / 32][48];
    const int warp = threadIdx.x >> 5;
    const int lane = threadIdx.x & 31;
    float* V = s_v[warp];

    // One-time per-warp: 16 packed (lo,hi) byte-offset regs (coalesced LDGs).
    unsigned pk[NITER];
    #pragma unroll
    for (int i = 0; i < NITER; i++) pk[i] = g_off.v[i * 32 + lane];

    const unsigned d0 = g_dec.v[lane];
    const unsigned d1 = g_dec.v[(lane + 32 < NVALS) ? lane + 32 : NVALS - 1];

    const int row0 = (blockIdx.x * (NTHREADS / 32) + warp) * RPW;

    // prefetch first row's x (lanes 0..7; others hold identity 1.0)
    float xv = 1.0f;
    if (row0 < nrows && lane < DIM) xv = x[(size_t)row0 * DIM + lane];

    #pragma unroll 1
    for (int r = 0; r < RPW; r++) {
        const int row = row0 + r;
        if (row >= nrows) break;

        float xnext = 1.0f;
        if (r + 1 < RPW && row + 1 < nrows && lane < DIM)
            xnext = x[(size_t)(row + 1) * DIM + lane];

        // build the 45 pair values via warp shuffles
        const float a0 = __shfl_sync(0xffffffffu, xv, d0 & 15u);
        const float b0 = __shfl_sync(0xffffffffu, xv, d0 >> 4);
        const float a1 = __shfl_sync(0xffffffffu, xv, d1 & 15u);
        const float b1 = __shfl_sync(0xffffffffu, xv, d1 >> 4);
        __syncwarp();                         // prior row's reads done
        V[lane] = a0 * b0;
        if (lane < NVALS - 32) V[lane + 32] = a1 * b1;
        __syncwarp();                         // writes visible

        const char* Vb = (const char*)V;
        float* o = out + (size_t)row * NTERMS + lane;
        #pragma unroll
        for (int i = 0; i < NITER; i++) {
            const unsigned p = pk[i];
            const float va = *(const float*)(Vb + (p & 255u));
            const float vb = *(const float*)(Vb + (p >> 8));
            if (i < NITER - 1 || lane < NTERMS - 32 * (NITER - 1))   // lane < 15
                o[32 * i] = va * vb;          // coalesced store
        }

        xv = xnext;
    }
}

extern "C" void kernel_launch(void* const* d_in, const int* in_sizes, int n_in,
                              void* d_out, int out_size) {
    const float* x = (const float*)d_in[0];
    float* out = (float*)d_out;
    const int nrows = in_sizes[0] / DIM;
    const int rows_per_block = (NTHREADS / 32) * RPW;       // 64
    const int blocks = (nrows + rows_per_block - 1) / rows_per_block;  // 1024
    totaldegree_kernel<<<blocks, NTHREADS>>>(x, out, nrows);
}